// round 16
// baseline (speedup 1.0000x reference)
#include <cuda_runtime.h>
#include <cuda_fp16.h>
#include <math.h>
#include <stdint.h>

#define VOCAB 8192
#define N_TOK 8192
#define INTER 4352
#define EMB   512

// ---------------- scratch ----------------
__device__ __align__(16) __half g_A[(size_t)INTER * N_TOK];   // A: [k][m_u] fp16
__device__ __align__(16) __half g_W[(size_t)EMB * INTER];     // W2: [n][k] fp16
__device__ __align__(16) float g_h2[(size_t)N_TOK * EMB];     // h2 (unique rows) pre-BN2
__device__ __align__(16) int   g_cnt[VOCAB];
__device__ __align__(16) int   g_xt[N_TOK];
__device__ int   g_is64;
__device__ __align__(16) int   g_uval[VOCAB];                 // uid -> vocab value
__device__ __align__(16) float g_wrowf[VOCAB];                // uid -> count (0 beyond M_u)
__device__ __align__(16) int   g_uidv[VOCAB];                 // vocab -> uid
__device__ int   g_Mu, g_mpad;
__device__ __align__(16) float g_p1[64 * EMB];
__device__ __align__(16) float g_p2[64 * EMB];
__device__ float g_mul2[EMB];
__device__ float g_add2[EMB];

// ---------------- helpers ----------------
__device__ __forceinline__ float gelu_exact(float x) {
    return 0.5f * x * (1.0f + erff(x * 0.7071067811865476f));
}
__device__ __forceinline__ uint32_t smem_u32(const void* p) {
    uint32_t a;
    asm("{ .reg .u64 t; cvta.to.shared.u64 t, %1; cvt.u32.u64 %0, t; }" : "=r"(a) : "l"(p));
    return a;
}
__device__ __forceinline__ void cp_async16(uint32_t dst, const void* src) {
    asm volatile("cp.async.cg.shared.global [%0], [%1], 16;" :: "r"(dst), "l"(src));
}
#define CP_COMMIT() asm volatile("cp.async.commit_group;" ::: "memory")
#define CP_WAIT(n)  asm volatile("cp.async.wait_group %0;" :: "n"(n) : "memory")

__device__ __forceinline__ void mma_f16(float* d, const uint32_t* a, const uint32_t* b) {
    asm volatile(
        "mma.sync.aligned.m16n8k16.row.col.f32.f16.f16.f32 "
        "{%0,%1,%2,%3}, {%4,%5,%6,%7}, {%8,%9}, {%0,%1,%2,%3};"
        : "+f"(d[0]), "+f"(d[1]), "+f"(d[2]), "+f"(d[3])
        : "r"(a[0]), "r"(a[1]), "r"(a[2]), "r"(a[3]), "r"(b[0]), "r"(b[1]));
}
__device__ __forceinline__ void ldsm_x4(uint32_t* r, uint32_t addr) {
    asm volatile("ldmatrix.sync.aligned.m8n8.x4.shared.b16 {%0,%1,%2,%3}, [%4];"
        : "=r"(r[0]), "=r"(r[1]), "=r"(r[2]), "=r"(r[3]) : "r"(addr));
}
__device__ __forceinline__ void ldsm_x4_t(uint32_t* r, uint32_t addr) {
    asm volatile("ldmatrix.sync.aligned.m8n8.x4.trans.shared.b16 {%0,%1,%2,%3}, [%4];"
        : "=r"(r[0]), "=r"(r[1]), "=r"(r[2]), "=r"(r[3]) : "r"(addr));
}

// ---------------- K0a: dtype detect + zero histogram ----------------
__global__ void detect_k(const int* __restrict__ xt_raw) {
    __shared__ int nz;
    if (threadIdx.x == 0) nz = 0;
    __syncthreads();
    int any = 0;
    for (int i = threadIdx.x; i < N_TOK / 2; i += 1024)
        any |= (xt_raw[2 * i + 1] != 0);
    if (any) atomicOr(&nz, 1);
    #pragma unroll
    for (int r = 0; r < VOCAB / 1024; r++)
        g_cnt[r * 1024 + threadIdx.x] = 0;
    __syncthreads();
    if (threadIdx.x == 0) g_is64 = (nz == 0);
}

// ---------------- K0b: normalize indices + histogram ----------------
__global__ void norm_hist_k(const int* __restrict__ xt_raw) {
    int n = blockIdx.x * 256 + threadIdx.x;
    int v = g_is64 ? xt_raw[2 * n] : xt_raw[n];
    g_xt[n] = v;
    atomicAdd(&g_cnt[v], 1);
}

// ---------------- K0c: exclusive scan -> unique-token compaction ----------------
__global__ __launch_bounds__(1024) void scan_k() {
    __shared__ int wsum[32];
    __shared__ int s_total;
    const int tid = threadIdx.x;
    const int lane = tid & 31, wid = tid >> 5;
    const int base = tid * 8;
    int c[8], pre[8], s = 0;
    #pragma unroll
    for (int j = 0; j < 8; j++) {
        c[j] = g_cnt[base + j];
        pre[j] = s;
        s += (c[j] > 0);
    }
    int v = s;                                   // inclusive warp scan
    #pragma unroll
    for (int o = 1; o < 32; o <<= 1) {
        int t = __shfl_up_sync(0xffffffffu, v, o);
        if (lane >= o) v += t;
    }
    if (lane == 31) wsum[wid] = v;
    __syncthreads();
    if (wid == 0) {
        int wv = wsum[lane];
        #pragma unroll
        for (int o = 1; o < 32; o <<= 1) {
            int t = __shfl_up_sync(0xffffffffu, wv, o);
            if (lane >= o) wv += t;
        }
        wsum[lane] = wv;
        if (lane == 31) s_total = wv;
    }
    __syncthreads();
    const int excl = v - s + (wid > 0 ? wsum[wid - 1] : 0);
    #pragma unroll
    for (int j = 0; j < 8; j++) {
        if (c[j] > 0) {
            int uid = excl + pre[j];
            g_uval[uid]  = base + j;
            g_wrowf[uid] = (float)c[j];
            g_uidv[base + j] = uid;
        }
    }
    __syncthreads();
    const int total = s_total;
    for (int i = tid; i < VOCAB; i += 1024)
        if (i >= total) { g_uval[i] = 0; g_wrowf[i] = 0.f; }
    if (tid == 0) { g_Mu = total; g_mpad = (total + 127) & ~127; }
}

// ---------------- K3: fused gather + BN1 + gelu -> A[k][uid] fp16 ----------------
__global__ __launch_bounds__(256) void gather_bn1_k(
    const float* __restrict__ W1,
    const float* __restrict__ g1, const float* __restrict__ beta1)
{
    __shared__ __align__(16) float row[VOCAB];
    __shared__ float red[16];
    const int i   = blockIdx.x;
    const int tid = threadIdx.x;
    const float* wrow = W1 + (size_t)i * VOCAB;

    float s1 = 0.f, s2 = 0.f;
    for (int idx = tid; idx < VOCAB / 4; idx += 256) {
        float4 w = reinterpret_cast<const float4*>(wrow)[idx];
        int4   c = reinterpret_cast<const int4*>(g_cnt)[idx];
        reinterpret_cast<float4*>(row)[idx] = w;
        s1 += (float)c.x * w.x + (float)c.y * w.y + (float)c.z * w.z + (float)c.w * w.w;
        s2 += (float)c.x * w.x * w.x + (float)c.y * w.y * w.y
            + (float)c.z * w.z * w.z + (float)c.w * w.w * w.w;
    }
    #pragma unroll
    for (int o = 16; o > 0; o >>= 1) {
        s1 += __shfl_down_sync(0xffffffffu, s1, o);
        s2 += __shfl_down_sync(0xffffffffu, s2, o);
    }
    if ((tid & 31) == 0) { red[tid >> 5] = s1; red[8 + (tid >> 5)] = s2; }
    __syncthreads();

    float t1 = 0.f, t2 = 0.f;
    #pragma unroll
    for (int w = 0; w < 8; w++) { t1 += red[w]; t2 += red[8 + w]; }
    const float mean = t1 * (1.f / (float)N_TOK);
    const float var  = t2 * (1.f / (float)N_TOK) - mean * mean;
    const float mul  = g1[i] * rsqrtf(var + 1e-5f);
    const float beta = beta1[i];

    const int mpad = g_mpad;
    __half* dst = g_A + (size_t)i * N_TOK;
    #pragma unroll 4
    for (int n = tid; n < mpad; n += 256) {
        int c = g_uval[n];
        float x = (row[c] - mean) * mul + beta;
        dst[n] = __float2half_rn(gelu_exact(x));
    }
}

// ---------------- K3b: convert W2 -> fp16 ----------------
__global__ void conv_w2_k(const float* __restrict__ W2) {
    int i = blockIdx.x * 256 + threadIdx.x;
    g_W[i] = __float2half_rn(W2[i]);
}

// ---------------- K4: fp16 mma GEMM on unique rows + weighted BN2 partials -------
#define BK 32
#define BN 256
#define NSTAGE (INTER / BK)                 // 136
#define OFF_A 0
#define OFF_B 8192
#define STAGE_BYTES 28672                   // 28 KB
#define GEMM_SMEM (3 * STAGE_BYTES)         // 84 KB

__device__ __forceinline__ void gemm_issue(uint32_t sb, int s, int m0, int n0, int tid) {
    const int k0 = s * BK;
    const uint32_t base = sb + (uint32_t)((s % 3) * STAGE_BYTES);
    #pragma unroll
    for (int t = 0; t < 2; t++) {
        int idx = tid + t * 256;
        int k = idx >> 4, c = idx & 15;
        uint32_t off = (uint32_t)(k * 256 + ((c * 16) ^ ((k & 7) << 4)));
        cp_async16(base + OFF_A + off, g_A + (size_t)(k0 + k) * N_TOK + m0 + c * 8);
    }
    #pragma unroll
    for (int t = 0; t < 4; t++) {
        int idx = tid + t * 256;
        int n = idx >> 2, c = idx & 3;
        uint32_t off = (uint32_t)(n * 80 + c * 16);
        cp_async16(base + OFF_B + off, g_W + (size_t)(n0 + n) * INTER + k0 + c * 8);
    }
    CP_COMMIT();
}

__global__ __launch_bounds__(256, 1) void gemm_mma_k(const float* __restrict__ b2) {
    extern __shared__ __align__(16) char smem[];
    const uint32_t sb = smem_u32(smem);

    const int tid    = threadIdx.x;
    const int m0 = blockIdx.x * 128;
    const int n0 = blockIdx.y * BN;

    const int mpad = g_mpad;
    if (m0 >= mpad) {                       // inactive tile: zero partials, exit
        g_p1[blockIdx.x * EMB + n0 + tid] = 0.f;
        g_p2[blockIdx.x * EMB + n0 + tid] = 0.f;
        return;
    }

    const int lane   = tid & 31;
    const int wid    = tid >> 5;
    const int warp_m = wid & 1;
    const int warp_n = wid >> 1;
    const int g      = lane >> 2;
    const int ct     = lane & 3;

    const int quad = lane >> 3, wi = lane & 7;
    const int a_k   = (quad >= 2 ? 8 : 0) + wi;
    const int a_mof = (warp_m * 64 + ((quad & 1) ? 8 : 0)) * 2;
    const uint32_t a_xor = (uint32_t)((a_k & 7) << 4);
    const int b_n  = warp_n * 64 + ((quad & 2) ? 8 : 0) + wi;
    const int b_kb = (quad & 1) ? 16 : 0;

    float acc[4][8][4];
    #pragma unroll
    for (int i = 0; i < 4; i++)
        #pragma unroll
        for (int j = 0; j < 8; j++)
            #pragma unroll
            for (int c = 0; c < 4; c++) acc[i][j][c] = 0.f;

    gemm_issue(sb, 0, m0, n0, tid);
    gemm_issue(sb, 1, m0, n0, tid);

    for (int s = 0; s < NSTAGE; s++) {
        if (s + 1 < NSTAGE) CP_WAIT(1); else CP_WAIT(0);
        __syncthreads();
        if (s + 2 < NSTAGE) gemm_issue(sb, s + 2, m0, n0, tid);

        const uint32_t stg = sb + (uint32_t)((s % 3) * STAGE_BYTES);

        #pragma unroll
        for (int ks = 0; ks < 2; ks++) {
            const uint32_t a_row  = stg + (uint32_t)((ks * 16 + a_k) * 256);
            const uint32_t b_base = stg + (uint32_t)(b_n * 80 + ks * 32 + b_kb);

            uint32_t a[4][4], b[4][4];
            #pragma unroll
            for (int mt = 0; mt < 4; mt++) {
                uint32_t moff = ((uint32_t)(a_mof + mt * 32)) ^ a_xor;
                ldsm_x4_t(a[mt], a_row + OFF_A + moff);
            }
            #pragma unroll
            for (int p = 0; p < 4; p++)
                ldsm_x4(b[p], b_base + OFF_B + (uint32_t)(p * 16 * 80));
            #pragma unroll
            for (int mt = 0; mt < 4; mt++)
                #pragma unroll
                for (int p = 0; p < 4; p++) {
                    mma_f16(acc[mt][2 * p],     a[mt], &b[p][0]);
                    mma_f16(acc[mt][2 * p + 1], a[mt], &b[p][2]);
                }
        }
    }

    // ---- epilogue: h2 = acc + bias; weighted BN2 partials (w = token count) ----
    float* sbuf = reinterpret_cast<float*>(smem);
    __syncthreads();

    float wrow[4][2];
    #pragma unroll
    for (int mt = 0; mt < 4; mt++) {
        const int m = m0 + warp_m * 64 + mt * 16 + g;
        wrow[mt][0] = g_wrowf[m];
        wrow[mt][1] = g_wrowf[m + 8];
    }

    #pragma unroll
    for (int nt = 0; nt < 8; nt++) {
        const int ncol = warp_n * 64 + nt * 8 + ct * 2;
        const int n = n0 + ncol;
        const float bx = __ldg(b2 + n), by = __ldg(b2 + n + 1);
        float sx1 = 0.f, sx2 = 0.f, sy1 = 0.f, sy2 = 0.f;
        #pragma unroll
        for (int mt = 0; mt < 4; mt++) {
            const int m = m0 + warp_m * 64 + mt * 16 + g;
            float v00 = acc[mt][nt][0] + bx, v01 = acc[mt][nt][1] + by;
            float v10 = acc[mt][nt][2] + bx, v11 = acc[mt][nt][3] + by;
            *reinterpret_cast<float2*>(&g_h2[(size_t)m * EMB + n])       = make_float2(v00, v01);
            *reinterpret_cast<float2*>(&g_h2[(size_t)(m + 8) * EMB + n]) = make_float2(v10, v11);
            const float wA = wrow[mt][0], wB = wrow[mt][1];
            sx1 += wA * v00 + wB * v10; sx2 += wA * v00 * v00 + wB * v10 * v10;
            sy1 += wA * v01 + wB * v11; sy2 += wA * v01 * v01 + wB * v11 * v11;
        }
        #pragma unroll
        for (int o = 4; o <= 16; o <<= 1) {
            sx1 += __shfl_xor_sync(0xffffffffu, sx1, o);
            sx2 += __shfl_xor_sync(0xffffffffu, sx2, o);
            sy1 += __shfl_xor_sync(0xffffffffu, sy1, o);
            sy2 += __shfl_xor_sync(0xffffffffu, sy2, o);
        }
        if (g == 0) {
            float* p = sbuf + ((warp_m * BN + ncol) << 1);
            p[0] = sx1; p[1] = sx2; p[2] = sy1; p[3] = sy2;
        }
    }
    __syncthreads();
    {
        const int col = tid;
        float p1 = sbuf[(col << 1)] + sbuf[((BN + col) << 1)];
        float p2 = sbuf[(col << 1) + 1] + sbuf[((BN + col) << 1) + 1];
        g_p1[blockIdx.x * EMB + n0 + col] = p1;
        g_p2[blockIdx.x * EMB + n0 + col] = p2;
    }
}

// ---------------- K6: finalize BN2 ----------------
__global__ __launch_bounds__(512) void stats_final_k(
    const float* __restrict__ g2, const float* __restrict__ beta2)
{
    const int e = threadIdx.x;
    float s1 = 0.f, s2 = 0.f;
    #pragma unroll
    for (int b = 0; b < 64; b++) { s1 += g_p1[b * EMB + e]; s2 += g_p2[b * EMB + e]; }
    float m = s1 * (1.f / (float)N_TOK);
    float v = s2 * (1.f / (float)N_TOK) - m * m;
    float mul = g2[e] * rsqrtf(v + 1e-5f);
    g_mul2[e] = mul;
    g_add2[e] = beta2[e] - mul * m;
}

// ---------------- K7: BN2 apply + gelu -> out (uid indirection) ----------------
__global__ __launch_bounds__(256) void final_k(float* __restrict__ out) {
    __shared__ int s_uid;
    const int n    = blockIdx.x >> 1;
    const int half = blockIdx.x & 1;
    if (threadIdx.x == 0) s_uid = g_uidv[g_xt[n]];
    __syncthreads();
    const int e = half * 256 + threadIdx.x;
    const float x = fmaf(g_mul2[e], g_h2[(size_t)s_uid * EMB + e], g_add2[e]);
    out[(size_t)n * EMB + e] = gelu_exact(x);
}

// ---------------- launch ----------------
extern "C" void kernel_launch(void* const* d_in, const int* in_sizes, int n_in,
                              void* d_out, int out_size)
{
    const int*   x_t_raw = (const int*)d_in[0];
    const float* W1    = (const float*)d_in[1];
    const float* g1    = (const float*)d_in[3];
    const float* beta1 = (const float*)d_in[4];
    const float* W2    = (const float*)d_in[5];
    const float* b2    = (const float*)d_in[6];
    const float* g2    = (const float*)d_in[7];
    const float* beta2 = (const float*)d_in[8];
    float* out = (float*)d_out;

    cudaFuncSetAttribute(gemm_mma_k, cudaFuncAttributeMaxDynamicSharedMemorySize, GEMM_SMEM);

    conv_w2_k<<<(EMB * INTER) / 256, 256>>>(W2);
    detect_k<<<1, 1024>>>(x_t_raw);
    norm_hist_k<<<N_TOK / 256, 256>>>(x_t_raw);
    scan_k<<<1, 1024>>>();
    gather_bn1_k<<<INTER, 256>>>(W1, g1, beta1);
    gemm_mma_k<<<dim3(N_TOK / 128, EMB / BN), 256, GEMM_SMEM>>>(b2);
    stats_final_k<<<1, 512>>>(g2, beta2);
    final_k<<<2 * N_TOK, 256>>>(out);
}

// round 17
// speedup vs baseline: 1.0454x; 1.0454x over previous
#include <cuda_runtime.h>
#include <cuda_fp16.h>
#include <math.h>
#include <stdint.h>

#define VOCAB 8192
#define N_TOK 8192
#define INTER 4352
#define EMB   512
#define SPLITK 4

// ---------------- scratch ----------------
__device__ __align__(16) __half g_A[(size_t)INTER * N_TOK];   // A: [k][uid] fp16
__device__ __align__(16) __half g_W[(size_t)EMB * INTER];     // W2: [n][k] fp16
__device__ __align__(16) float g_part[(size_t)SPLITK * N_TOK * EMB]; // split-K partials
__device__ __align__(16) float g_h2[(size_t)N_TOK * EMB];     // h2 (unique rows) pre-BN2
__device__ __align__(16) int   g_cnt[VOCAB];
__device__ __align__(16) float g_cntf[VOCAB];
__device__ __align__(16) int   g_xt[N_TOK];
__device__ int   g_is64;
__device__ __align__(16) int   g_uval[VOCAB];                 // uid -> vocab value
__device__ __align__(16) float g_wrowf[VOCAB];                // uid -> count (0 beyond M_u)
__device__ __align__(16) int   g_uidv[VOCAB];                 // vocab -> uid
__device__ int   g_Mu, g_mpad;
__device__ __align__(16) float g_p1[256 * EMB];
__device__ __align__(16) float g_p2[256 * EMB];
__device__ float g_mul2[EMB];
__device__ float g_add2[EMB];

// ---------------- helpers ----------------
__device__ __forceinline__ float gelu_exact(float x) {
    return 0.5f * x * (1.0f + erff(x * 0.7071067811865476f));
}
__device__ __forceinline__ uint32_t smem_u32(const void* p) {
    uint32_t a;
    asm("{ .reg .u64 t; cvta.to.shared.u64 t, %1; cvt.u32.u64 %0, t; }" : "=r"(a) : "l"(p));
    return a;
}
__device__ __forceinline__ void cp_async16(uint32_t dst, const void* src) {
    asm volatile("cp.async.cg.shared.global [%0], [%1], 16;" :: "r"(dst), "l"(src));
}
#define CP_COMMIT() asm volatile("cp.async.commit_group;" ::: "memory")
#define CP_WAIT(n)  asm volatile("cp.async.wait_group %0;" :: "n"(n) : "memory")

__device__ __forceinline__ void mma_f16(float* d, const uint32_t* a, const uint32_t* b) {
    asm volatile(
        "mma.sync.aligned.m16n8k16.row.col.f32.f16.f16.f32 "
        "{%0,%1,%2,%3}, {%4,%5,%6,%7}, {%8,%9}, {%0,%1,%2,%3};"
        : "+f"(d[0]), "+f"(d[1]), "+f"(d[2]), "+f"(d[3])
        : "r"(a[0]), "r"(a[1]), "r"(a[2]), "r"(a[3]), "r"(b[0]), "r"(b[1]));
}
__device__ __forceinline__ void ldsm_x4(uint32_t* r, uint32_t addr) {
    asm volatile("ldmatrix.sync.aligned.m8n8.x4.shared.b16 {%0,%1,%2,%3}, [%4];"
        : "=r"(r[0]), "=r"(r[1]), "=r"(r[2]), "=r"(r[3]) : "r"(addr));
}
__device__ __forceinline__ void ldsm_x4_t(uint32_t* r, uint32_t addr) {
    asm volatile("ldmatrix.sync.aligned.m8n8.x4.trans.shared.b16 {%0,%1,%2,%3}, [%4];"
        : "=r"(r[0]), "=r"(r[1]), "=r"(r[2]), "=r"(r[3]) : "r"(addr));
}

// ---------------- K0a: dtype detect + zero histogram ----------------
__global__ void detect_k(const int* __restrict__ xt_raw) {
    __shared__ int nz;
    if (threadIdx.x == 0) nz = 0;
    __syncthreads();
    int any = 0;
    for (int i = threadIdx.x; i < N_TOK / 2; i += 1024)
        any |= (xt_raw[2 * i + 1] != 0);
    if (any) atomicOr(&nz, 1);
    #pragma unroll
    for (int r = 0; r < VOCAB / 1024; r++)
        g_cnt[r * 1024 + threadIdx.x] = 0;
    __syncthreads();
    if (threadIdx.x == 0) g_is64 = (nz == 0);
}

// ---------------- K0b: normalize indices + histogram ----------------
__global__ void norm_hist_k(const int* __restrict__ xt_raw) {
    int n = blockIdx.x * 256 + threadIdx.x;
    int v = g_is64 ? xt_raw[2 * n] : xt_raw[n];
    g_xt[n] = v;
    atomicAdd(&g_cnt[v], 1);
}

// ---------------- K0c: exclusive scan -> unique-token compaction (+cntf) --------
__global__ __launch_bounds__(1024) void scan_k() {
    __shared__ int wsum[32];
    __shared__ int s_total;
    const int tid = threadIdx.x;
    const int lane = tid & 31, wid = tid >> 5;
    const int base = tid * 8;
    int c[8], pre[8], s = 0;
    #pragma unroll
    for (int j = 0; j < 8; j++) {
        c[j] = g_cnt[base + j];
        g_cntf[base + j] = (float)c[j];
        pre[j] = s;
        s += (c[j] > 0);
    }
    int v = s;
    #pragma unroll
    for (int o = 1; o < 32; o <<= 1) {
        int t = __shfl_up_sync(0xffffffffu, v, o);
        if (lane >= o) v += t;
    }
    if (lane == 31) wsum[wid] = v;
    __syncthreads();
    if (wid == 0) {
        int wv = wsum[lane];
        #pragma unroll
        for (int o = 1; o < 32; o <<= 1) {
            int t = __shfl_up_sync(0xffffffffu, wv, o);
            if (lane >= o) wv += t;
        }
        wsum[lane] = wv;
        if (lane == 31) s_total = wv;
    }
    __syncthreads();
    const int excl = v - s + (wid > 0 ? wsum[wid - 1] : 0);
    #pragma unroll
    for (int j = 0; j < 8; j++) {
        if (c[j] > 0) {
            int uid = excl + pre[j];
            g_uval[uid]  = base + j;
            g_wrowf[uid] = (float)c[j];
            g_uidv[base + j] = uid;
        }
    }
    __syncthreads();
    const int total = s_total;
    for (int i = tid; i < VOCAB; i += 1024)
        if (i >= total) { g_uval[i] = 0; g_wrowf[i] = 0.f; }
    if (tid == 0) { g_Mu = total; g_mpad = (total + 127) & ~127; }
}

// ---------------- K3: fused gather + BN1 + gelu -> A[k][uid] fp16 ----------------
__global__ __launch_bounds__(256) void gather_bn1_k(
    const float* __restrict__ W1,
    const float* __restrict__ g1, const float* __restrict__ beta1)
{
    __shared__ __align__(16) float row[VOCAB];
    __shared__ float red[16];
    const int i   = blockIdx.x;
    const int tid = threadIdx.x;
    const float* wrow = W1 + (size_t)i * VOCAB;

    float s1 = 0.f, s2 = 0.f;
    for (int idx = tid; idx < VOCAB / 4; idx += 256) {
        float4 w = reinterpret_cast<const float4*>(wrow)[idx];
        float4 c = reinterpret_cast<const float4*>(g_cntf)[idx];
        reinterpret_cast<float4*>(row)[idx] = w;
        s1 += c.x * w.x + c.y * w.y + c.z * w.z + c.w * w.w;
        s2 += c.x * w.x * w.x + c.y * w.y * w.y + c.z * w.z * w.z + c.w * w.w * w.w;
    }
    #pragma unroll
    for (int o = 16; o > 0; o >>= 1) {
        s1 += __shfl_down_sync(0xffffffffu, s1, o);
        s2 += __shfl_down_sync(0xffffffffu, s2, o);
    }
    if ((tid & 31) == 0) { red[tid >> 5] = s1; red[8 + (tid >> 5)] = s2; }
    __syncthreads();

    float t1 = 0.f, t2 = 0.f;
    #pragma unroll
    for (int w = 0; w < 8; w++) { t1 += red[w]; t2 += red[8 + w]; }
    const float mean = t1 * (1.f / (float)N_TOK);
    const float var  = t2 * (1.f / (float)N_TOK) - mean * mean;
    const float mul  = g1[i] * rsqrtf(var + 1e-5f);
    const float beta = beta1[i];

    const int mpad = g_mpad;
    __half* dst = g_A + (size_t)i * N_TOK;
    for (int n4 = tid * 4; n4 < mpad; n4 += 1024) {
        int4 u = *reinterpret_cast<const int4*>(&g_uval[n4]);
        float y0 = gelu_exact((row[u.x] - mean) * mul + beta);
        float y1 = gelu_exact((row[u.y] - mean) * mul + beta);
        float y2 = gelu_exact((row[u.z] - mean) * mul + beta);
        float y3 = gelu_exact((row[u.w] - mean) * mul + beta);
        __half2 h01 = __floats2half2_rn(y0, y1);
        __half2 h23 = __floats2half2_rn(y2, y3);
        uint2 pk;
        pk.x = *reinterpret_cast<uint32_t*>(&h01);
        pk.y = *reinterpret_cast<uint32_t*>(&h23);
        *reinterpret_cast<uint2*>(&dst[n4]) = pk;
    }
}

// ---------------- K3b: convert W2 -> fp16 ----------------
__global__ void conv_w2_k(const float* __restrict__ W2) {
    int i = blockIdx.x * 256 + threadIdx.x;
    g_W[i] = __float2half_rn(W2[i]);
}

// ---------------- K4: fp16 mma GEMM, split-K partials ----------------
#define BK 32
#define BN 256
#define KSTAGES (INTER / BK / SPLITK)       // 34 stages per split
#define OFF_A 0
#define OFF_B 8192
#define STAGE_BYTES 28672                   // 28 KB
#define GEMM_SMEM (3 * STAGE_BYTES)         // 84 KB

__device__ __forceinline__ void gemm_issue(uint32_t sb, int s, int m0, int n0, int tid) {
    const int k0 = s * BK;
    const uint32_t base = sb + (uint32_t)((s % 3) * STAGE_BYTES);
    #pragma unroll
    for (int t = 0; t < 2; t++) {
        int idx = tid + t * 256;
        int k = idx >> 4, c = idx & 15;
        uint32_t off = (uint32_t)(k * 256 + ((c * 16) ^ ((k & 7) << 4)));
        cp_async16(base + OFF_A + off, g_A + (size_t)(k0 + k) * N_TOK + m0 + c * 8);
    }
    #pragma unroll
    for (int t = 0; t < 4; t++) {
        int idx = tid + t * 256;
        int n = idx >> 2, c = idx & 3;
        uint32_t off = (uint32_t)(n * 80 + c * 16);
        cp_async16(base + OFF_B + off, g_W + (size_t)(n0 + n) * INTER + k0 + c * 8);
    }
    CP_COMMIT();
}

__global__ __launch_bounds__(256, 1) void gemm_mma_k() {
    extern __shared__ __align__(16) char smem[];
    const uint32_t sb = smem_u32(smem);

    const int tid = threadIdx.x;
    const int m0 = blockIdx.x * 128;
    const int n0 = blockIdx.y * BN;
    const int kz = blockIdx.z;

    if (m0 >= g_mpad) return;               // inactive tile (combine never reads it)

    const int lane   = tid & 31;
    const int wid    = tid >> 5;
    const int warp_m = wid & 1;
    const int warp_n = wid >> 1;
    const int g      = lane >> 2;
    const int ct     = lane & 3;

    const int quad = lane >> 3, wi = lane & 7;
    const int a_k   = (quad >= 2 ? 8 : 0) + wi;
    const int a_mof = (warp_m * 64 + ((quad & 1) ? 8 : 0)) * 2;
    const uint32_t a_xor = (uint32_t)((a_k & 7) << 4);
    const int b_n  = warp_n * 64 + ((quad & 2) ? 8 : 0) + wi;
    const int b_kb = (quad & 1) ? 16 : 0;

    float acc[4][8][4];
    #pragma unroll
    for (int i = 0; i < 4; i++)
        #pragma unroll
        for (int j = 0; j < 8; j++)
            #pragma unroll
            for (int c = 0; c < 4; c++) acc[i][j][c] = 0.f;

    const int S0 = kz * KSTAGES;
    gemm_issue(sb, S0, m0, n0, tid);
    gemm_issue(sb, S0 + 1, m0, n0, tid);

    for (int s = 0; s < KSTAGES; s++) {
        if (s + 1 < KSTAGES) CP_WAIT(1); else CP_WAIT(0);
        __syncthreads();
        if (s + 2 < KSTAGES) gemm_issue(sb, S0 + s + 2, m0, n0, tid);

        const uint32_t stg = sb + (uint32_t)(((S0 + s) % 3) * STAGE_BYTES);

        #pragma unroll
        for (int ks = 0; ks < 2; ks++) {
            const uint32_t a_row  = stg + (uint32_t)((ks * 16 + a_k) * 256);
            const uint32_t b_base = stg + (uint32_t)(b_n * 80 + ks * 32 + b_kb);

            uint32_t a[4][4], b[4][4];
            #pragma unroll
            for (int mt = 0; mt < 4; mt++) {
                uint32_t moff = ((uint32_t)(a_mof + mt * 32)) ^ a_xor;
                ldsm_x4_t(a[mt], a_row + OFF_A + moff);
            }
            #pragma unroll
            for (int p = 0; p < 4; p++)
                ldsm_x4(b[p], b_base + OFF_B + (uint32_t)(p * 16 * 80));
            #pragma unroll
            for (int mt = 0; mt < 4; mt++)
                #pragma unroll
                for (int p = 0; p < 4; p++) {
                    mma_f16(acc[mt][2 * p],     a[mt], &b[p][0]);
                    mma_f16(acc[mt][2 * p + 1], a[mt], &b[p][2]);
                }
        }
    }

    // store raw partials to g_part[kz]
    float* dst = g_part + (size_t)kz * N_TOK * EMB;
    #pragma unroll
    for (int nt = 0; nt < 8; nt++) {
        const int n = n0 + warp_n * 64 + nt * 8 + ct * 2;
        #pragma unroll
        for (int mt = 0; mt < 4; mt++) {
            const int m = m0 + warp_m * 64 + mt * 16 + g;
            *reinterpret_cast<float2*>(&dst[(size_t)m * EMB + n]) =
                make_float2(acc[mt][nt][0], acc[mt][nt][1]);
            *reinterpret_cast<float2*>(&dst[(size_t)(m + 8) * EMB + n]) =
                make_float2(acc[mt][nt][2], acc[mt][nt][3]);
        }
    }
}

// ---------------- K5: combine split-K partials + bias -> h2, weighted BN2 partials
__global__ __launch_bounds__(512) void combine_k(const float* __restrict__ b2) {
    const int b = blockIdx.x;               // 32 unique rows per block
    const int e = threadIdx.x;              // 512 channels
    const int mpad = g_mpad;
    if (b * 32 >= mpad) {
        g_p1[b * EMB + e] = 0.f;
        g_p2[b * EMB + e] = 0.f;
        return;
    }
    const float bias = b2[e];
    const size_t P = (size_t)N_TOK * EMB;
    float s1 = 0.f, s2 = 0.f;
    #pragma unroll 4
    for (int r = 0; r < 32; r++) {
        const int row = b * 32 + r;
        const size_t off = (size_t)row * EMB + e;
        float v = ((g_part[off] + g_part[P + off]) + g_part[2 * P + off])
                  + g_part[3 * P + off] + bias;
        g_h2[off] = v;
        const float w = g_wrowf[row];
        s1 += w * v;
        s2 += w * v * v;
    }
    g_p1[b * EMB + e] = s1;
    g_p2[b * EMB + e] = s2;
}

// ---------------- K6: finalize BN2 ----------------
__global__ __launch_bounds__(512) void stats_final_k(
    const float* __restrict__ g2, const float* __restrict__ beta2)
{
    const int e = threadIdx.x;
    float s1 = 0.f, s2 = 0.f;
    #pragma unroll 8
    for (int b = 0; b < 256; b++) { s1 += g_p1[b * EMB + e]; s2 += g_p2[b * EMB + e]; }
    float m = s1 * (1.f / (float)N_TOK);
    float v = s2 * (1.f / (float)N_TOK) - m * m;
    float mul = g2[e] * rsqrtf(v + 1e-5f);
    g_mul2[e] = mul;
    g_add2[e] = beta2[e] - mul * m;
}

// ---------------- K7: BN2 apply + gelu -> out (uid indirection) ----------------
__global__ __launch_bounds__(512) void final_k(float* __restrict__ out) {
    __shared__ int s_uid;
    const int n = blockIdx.x;
    if (threadIdx.x == 0) s_uid = g_uidv[g_xt[n]];
    __syncthreads();
    const int e = threadIdx.x;
    const float x = fmaf(g_mul2[e], g_h2[(size_t)s_uid * EMB + e], g_add2[e]);
    out[(size_t)n * EMB + e] = gelu_exact(x);
}

// ---------------- launch ----------------
extern "C" void kernel_launch(void* const* d_in, const int* in_sizes, int n_in,
                              void* d_out, int out_size)
{
    const int*   x_t_raw = (const int*)d_in[0];
    const float* W1    = (const float*)d_in[1];
    const float* g1    = (const float*)d_in[3];
    const float* beta1 = (const float*)d_in[4];
    const float* W2    = (const float*)d_in[5];
    const float* b2    = (const float*)d_in[6];
    const float* g2    = (const float*)d_in[7];
    const float* beta2 = (const float*)d_in[8];
    float* out = (float*)d_out;

    cudaFuncSetAttribute(gemm_mma_k, cudaFuncAttributeMaxDynamicSharedMemorySize, GEMM_SMEM);

    conv_w2_k<<<(EMB * INTER) / 256, 256>>>(W2);
    detect_k<<<1, 1024>>>(x_t_raw);
    norm_hist_k<<<N_TOK / 256, 256>>>(x_t_raw);
    scan_k<<<1, 1024>>>();
    gather_bn1_k<<<INTER, 256>>>(W1, g1, beta1);
    gemm_mma_k<<<dim3(N_TOK / 128, EMB / BN, SPLITK), 256, GEMM_SMEM>>>();
    combine_k<<<256, 512>>>(b2);
    stats_final_k<<<1, 512>>>(g2, beta2);
    final_k<<<N_TOK, 512>>>(out);
}